// round 6
// baseline (speedup 1.0000x reference)
#include <cuda_runtime.h>
#include <math.h>

#define BATCH 32
#define NIN   1024
#define NC    20
#define DIM   64
#define CD    (NC*DIM)   // 1280
#define CIN   128

// ---------------- scratch (device globals: no allocations allowed) ----------
__device__ float g_uhat[(size_t)BATCH * NIN * CD];   // 167.8 MB
__device__ float g_bij[BATCH * NIN * NC];            // routing logits
__device__ float g_spart[BATCH * NC * DIM];          // partial weighted sums (zero-init, re-zeroed each use)
__device__ float g_wsum[BATCH * NC];                 // partial weight sums
__device__ float g_v[BATCH * NC * DIM];              // v per iteration
__device__ float g_vn2[BATCH * NC];                  // |v|^2 per (b,class)

// ---------------- packed f32x2 helpers --------------------------------------
__device__ __forceinline__ void ffma2(unsigned long long &d,
                                      unsigned long long a,
                                      unsigned long long b) {
    asm("fma.rn.f32x2 %0, %1, %2, %0;" : "+l"(d) : "l"(a), "l"(b));
}
__device__ __forceinline__ float2 upk(unsigned long long v) {
    float2 f;
    asm("mov.b64 {%0, %1}, %2;" : "=f"(f.x), "=f"(f.y) : "l"(v));
    return f;
}

// ---------------- Kernel 1: u_hat GEMM --------------------------------------
// grid = (CD/256 = 5, NIN), block = 256.
// Block covers: one n, all 32 b, 256 consecutive cd rows.
// Thread tile: 4 b x 8 cd, inner loop over i in steps of 4 using f32x2 FMA.
__global__ __launch_bounds__(256)
void k_gemm(const float* __restrict__ x, const float* __restrict__ w1) {
    __shared__ float xs[32 * 132];   // padded rows (132) to break bank conflicts

    const int n      = blockIdx.y;
    const int cdBase = blockIdx.x * 256;
    const int t      = threadIdx.x;

    // stage x[:, n, :]  (32 x 128) into smem, coalesced
    for (int e = t; e < 32 * 128; e += 256) {
        int bb = e >> 7, i = e & 127;
        xs[bb * 132 + i] = x[((size_t)bb * NIN + n) * CIN + i];
    }
    __syncthreads();

    const int bg = t & 7;          // b-group: b = bg*4 + bi
    const int cg = t >> 3;         // cd-group: cd = cdBase + cg*8 + r
    const float* wp = w1 + ((size_t)n * CD + cdBase + cg * 8) * CIN;

    unsigned long long acc[4][8];
    #pragma unroll
    for (int bi = 0; bi < 4; bi++)
        #pragma unroll
        for (int r = 0; r < 8; r++) acc[bi][r] = 0ull;

    #pragma unroll 2
    for (int i0 = 0; i0 < CIN; i0 += 4) {
        ulonglong2 xq[4];
        #pragma unroll
        for (int bi = 0; bi < 4; bi++)
            xq[bi] = *(const ulonglong2*)(xs + (bg * 4 + bi) * 132 + i0);
        #pragma unroll
        for (int r = 0; r < 8; r++) {
            ulonglong2 wq = *(const ulonglong2*)(wp + r * CIN + i0);
            #pragma unroll
            for (int bi = 0; bi < 4; bi++) {
                ffma2(acc[bi][r], xq[bi].x, wq.x);
                ffma2(acc[bi][r], xq[bi].y, wq.y);
            }
        }
    }

    // epilogue: horizontal add of packed pairs, vectorized store
    #pragma unroll
    for (int bi = 0; bi < 4; bi++) {
        const int b = bg * 4 + bi;
        float o[8];
        #pragma unroll
        for (int r = 0; r < 8; r++) {
            float2 f = upk(acc[bi][r]);
            o[r] = f.x + f.y;
        }
        float* op = g_uhat + ((size_t)b * NIN + n) * CD + cdBase + cg * 8;
        *(float4*)(op)     = make_float4(o[0], o[1], o[2], o[3]);
        *(float4*)(op + 4) = make_float4(o[4], o[5], o[6], o[7]);
    }
}

// ---------------- Kernel 2: fused routing pass -------------------------------
// One pass over u_hat per iteration. grid = (NIN/32, BATCH), block = 256 (8 warps).
// Warp handles 4 n values; u_hat row (20x64) cached in registers (float2/lane).
// iter==0: uniform c. iter>=1: dd vs v_prev, b update, per-n softmax over classes.
__global__ __launch_bounds__(256)
void k_route(int iter) {
    __shared__ float v_s[CD];
    __shared__ float vn2_s[NC];
    __shared__ float sbuf[8][CD];
    __shared__ float wbuf[8][NC];

    const int b  = blockIdx.y;
    const int n0 = blockIdx.x * 32;
    const int t    = threadIdx.x;
    const int w    = t >> 5;
    const int lane = t & 31;

    if (iter > 0) {
        for (int e = t; e < CD; e += 256) v_s[e] = g_v[b * CD + e];
        if (t < NC) vn2_s[t] = g_vn2[b * NC + t];
    }
    __syncthreads();

    float2 sacc[NC];
    #pragma unroll
    for (int j = 0; j < NC; j++) sacc[j] = make_float2(0.f, 0.f);
    float cwacc = 0.f;

    for (int k = 0; k < 4; k++) {
        const int n = n0 + k * 8 + w;
        const float* up = g_uhat + ((size_t)b * NIN + n) * CD;

        float2 ur[NC];
        float myun2 = 0.f, mydot = 0.f;

        #pragma unroll
        for (int j = 0; j < NC; j++) {
            float2 u2 = *(const float2*)(up + j * DIM + 2 * lane);
            ur[j] = u2;
            if (iter > 0) {
                float2 v2 = *(const float2*)(v_s + j * DIM + 2 * lane);
                float p = u2.x * u2.x + u2.y * u2.y;
                float q = u2.x * v2.x + u2.y * v2.y;
                #pragma unroll
                for (int off = 16; off > 0; off >>= 1) {
                    p += __shfl_xor_sync(0xffffffffu, p, off);
                    q += __shfl_xor_sync(0xffffffffu, q, off);
                }
                if (lane == j) { myun2 = p; mydot = q; }
            }
        }

        float craw;
        if (iter == 0) {
            craw = 1.0f;
        } else {
            float bnew = -3.0e38f;
            if (lane < NC) {
                float un2 = myun2;
                float a   = sqrtf(un2) / (0.5f + un2);          // squash scale of u_hat
                float dd  = 1.0f - (a * a * un2 - 2.0f * a * mydot + vn2_s[lane]);
                if (iter == 1) {
                    bnew = dd;                                    // b was 0
                    g_bij[(b * NIN + n) * NC + lane] = dd;
                } else {
                    bnew = g_bij[(b * NIN + n) * NC + lane] + dd; // last iter: no store needed
                }
            }
            float m = bnew;
            #pragma unroll
            for (int off = 16; off > 0; off >>= 1)
                m = fmaxf(m, __shfl_xor_sync(0xffffffffu, m, off));
            float e = (lane < NC) ? __expf(bnew - m) : 0.0f;
            float ssum = e;
            #pragma unroll
            for (int off = 16; off > 0; off >>= 1)
                ssum += __shfl_xor_sync(0xffffffffu, ssum, off);
            craw = e / ssum;
        }

        // accumulate weighted sums (u_hat reused from registers)
        #pragma unroll
        for (int j = 0; j < NC; j++) {
            float cj = __shfl_sync(0xffffffffu, craw, j);
            sacc[j].x += cj * ur[j].x;
            sacc[j].y += cj * ur[j].y;
        }
        if (lane < NC) cwacc += craw;
    }

    // stage per-warp partials, block-reduce, one atomic per element per block
    #pragma unroll
    for (int j = 0; j < NC; j++)
        *(float2*)&sbuf[w][j * DIM + 2 * lane] = sacc[j];
    if (lane < NC) wbuf[w][lane] = cwacc;
    __syncthreads();

    for (int e = t; e < CD; e += 256) {
        float s = 0.f;
        #pragma unroll
        for (int ww = 0; ww < 8; ww++) s += sbuf[ww][e];
        atomicAdd(&g_spart[b * CD + e], s);
    }
    if (t < NC) {
        float s = 0.f;
        #pragma unroll
        for (int ww = 0; ww < 8; ww++) s += wbuf[ww][t];
        atomicAdd(&g_wsum[b * NC + t], s);
    }
}

// ---------------- Kernel 3: squash + (final) output --------------------------
// grid = BATCH*NC blocks, 64 threads (one per d). Re-zeros partials for next iter.
__global__ __launch_bounds__(64)
void k_squash(int final_iter, float* __restrict__ out) {
    const int bj = blockIdx.x;          // b*NC + j
    const int d  = threadIdx.x;
    const int lane = d & 31, wp = d >> 5;

    float sv = g_spart[bj * DIM + d];
    float ws = g_wsum[bj];
    float s  = sv / ws;

    float p = s * s;
    #pragma unroll
    for (int off = 16; off > 0; off >>= 1)
        p += __shfl_xor_sync(0xffffffffu, p, off);
    __shared__ float red[2];
    if (lane == 0) red[wp] = p;
    __syncthreads();
    float s2 = red[0] + red[1];

    float sc = sqrtf(s2) / (0.5f + s2);
    float v  = sc * s;

    g_v[bj * DIM + d] = v;
    if (d == 0) g_vn2[bj] = sc * sc * s2;

    // reset partials so next iteration / next graph replay starts clean
    g_spart[bj * DIM + d] = 0.0f;
    if (d == 0) g_wsum[bj] = 0.0f;

    if (final_iter) {
        out[bj * DIM + d] = v;                                  // poses [B,C,D,1] flattened
        if (d == 0)
            out[BATCH * NC * DIM + bj] = sqrtf(sc * sc * s2);   // activations [B,C,1]
    }
}

// ---------------- launch -----------------------------------------------------
extern "C" void kernel_launch(void* const* d_in, const int* in_sizes, int n_in,
                              void* d_out, int out_size) {
    const float* x  = (const float*)d_in[0];
    const float* w1 = (const float*)d_in[1];
    if (n_in >= 2 && in_sizes[0] > in_sizes[1]) {   // defensive: x is the smaller input
        x  = (const float*)d_in[1];
        w1 = (const float*)d_in[0];
    }
    float* out = (float*)d_out;

    k_gemm<<<dim3(CD / 256, NIN), 256>>>(x, w1);

    k_route<<<dim3(NIN / 32, BATCH), 256>>>(0);
    k_squash<<<BATCH * NC, 64>>>(0, out);

    k_route<<<dim3(NIN / 32, BATCH), 256>>>(1);
    k_squash<<<BATCH * NC, 64>>>(0, out);

    k_route<<<dim3(NIN / 32, BATCH), 256>>>(2);
    k_squash<<<BATCH * NC, 64>>>(1, out);
}